// round 12
// baseline (speedup 1.0000x reference)
#include <cuda_runtime.h>
#include <cuda_bf16.h>
#include <stdint.h>
#include <math.h>

#define CS 1024
#define NI 1024
#define NJ 1024
#define NH 16
#define ND 64
#define CZ 128

// ---------------- scratch (device globals; no allocation allowed) ----------
__device__ float g_gt[NI * CS];                       // sigmoid gate (fp32)
__device__ float g_z[(size_t)NH * NI * NJ];           // pair bias [h][i*NJ+j]
__device__ __nv_bfloat16 g_sh[NI * CS],  g_sl[NI * CS];
__device__ __nv_bfloat16 g_kih[NJ * CS], g_kil[NJ * CS];
__device__ __nv_bfloat16 g_Wqh[CS * CS], g_Wql[CS * CS];
__device__ __nv_bfloat16 g_Wkh[CS * CS], g_Wkl[CS * CS];
__device__ __nv_bfloat16 g_Wvh[CS * CS], g_Wvl[CS * CS];
__device__ __nv_bfloat16 g_Wgh[CS * CS], g_Wgl[CS * CS];
__device__ __nv_bfloat16 g_Woh[CS * CS], g_Wol[CS * CS];
__device__ __nv_bfloat16 g_qh[NI * CS],  g_ql[NI * CS];
__device__ __nv_bfloat16 g_kh[NJ * CS],  g_kl[NJ * CS];
__device__ __nv_bfloat16 g_vh[NJ * CS],  g_vl[NJ * CS];
__device__ __nv_bfloat16 g_goh[NI * CS], g_gol[NI * CS];

// ===================== mma.sync / cp.async helpers =========================
__device__ __forceinline__ uint32_t smem_u32(const void* p) {
    uint32_t r;
    asm("{ .reg .u64 t; cvta.to.shared.u64 t, %1; cvt.u32.u64 %0, t; }"
        : "=r"(r) : "l"(p));
    return r;
}
__device__ __forceinline__ void ldsm4(uint32_t* r, uint32_t a) {
    asm volatile("ldmatrix.sync.aligned.m8n8.x4.shared.b16 {%0,%1,%2,%3}, [%4];"
                 : "=r"(r[0]), "=r"(r[1]), "=r"(r[2]), "=r"(r[3]) : "r"(a));
}
__device__ __forceinline__ void ldsm4t(uint32_t* r, uint32_t a) {
    asm volatile("ldmatrix.sync.aligned.m8n8.x4.trans.shared.b16 {%0,%1,%2,%3}, [%4];"
                 : "=r"(r[0]), "=r"(r[1]), "=r"(r[2]), "=r"(r[3]) : "r"(a));
}
__device__ __forceinline__ void mma_bf16(float* d, const uint32_t* a,
                                         uint32_t b0, uint32_t b1) {
    asm volatile(
        "mma.sync.aligned.m16n8k16.row.col.f32.bf16.bf16.f32 "
        "{%0,%1,%2,%3}, {%4,%5,%6,%7}, {%8,%9}, {%0,%1,%2,%3};"
        : "+f"(d[0]), "+f"(d[1]), "+f"(d[2]), "+f"(d[3])
        : "r"(a[0]), "r"(a[1]), "r"(a[2]), "r"(a[3]), "r"(b0), "r"(b1));
}
__device__ __forceinline__ void cpa16(uint32_t s, const void* g) {
    asm volatile("cp.async.cg.shared.global [%0], [%1], 16;" :: "r"(s), "l"(g));
}
__device__ __forceinline__ void cpa_commit() {
    asm volatile("cp.async.commit_group;");
}
template <int N> __device__ __forceinline__ void cpa_wait() {
    asm volatile("cp.async.wait_group %0;" :: "n"(N));
}
__device__ __forceinline__ uint32_t pack2(__nv_bfloat16 a, __nv_bfloat16 b) {
    return (uint32_t)__bfloat16_as_ushort(a) |
           ((uint32_t)__bfloat16_as_ushort(b) << 16);
}
__device__ __forceinline__ void split4(float4 v, uint2* hi, uint2* lo) {
    __nv_bfloat16 h0 = __float2bfloat16_rn(v.x);
    __nv_bfloat16 h1 = __float2bfloat16_rn(v.y);
    __nv_bfloat16 h2 = __float2bfloat16_rn(v.z);
    __nv_bfloat16 h3 = __float2bfloat16_rn(v.w);
    hi->x = pack2(h0, h1); hi->y = pack2(h2, h3);
    lo->x = pack2(__float2bfloat16_rn(v.x - __bfloat162float(h0)),
                  __float2bfloat16_rn(v.y - __bfloat162float(h1)));
    lo->y = pack2(__float2bfloat16_rn(v.z - __bfloat162float(h2)),
                  __float2bfloat16_rn(v.w - __bfloat162float(h3)));
}
__device__ __forceinline__ void split2(float v0, float v1,
                                       uint32_t* hp, uint32_t* lp) {
    __nv_bfloat16 h0 = __float2bfloat16_rn(v0);
    __nv_bfloat16 h1 = __float2bfloat16_rn(v1);
    *hp = pack2(h0, h1);
    *lp = pack2(__float2bfloat16_rn(v0 - __bfloat162float(h0)),
                __float2bfloat16_rn(v1 - __bfloat162float(h1)));
}

// ============ preconvert: fp32 -> bf16 hi/lo for 7 matrices (1M each) ======
__global__ __launch_bounds__(256) void preconv(
    const float* __restrict__ s, const float* __restrict__ kin,
    const float* __restrict__ Wq, const float* __restrict__ Wk,
    const float* __restrict__ Wv, const float* __restrict__ Wg,
    const float* __restrict__ Wo)
{
    const float* src; __nv_bfloat16 *dh, *dl;
    switch (blockIdx.y) {
        case 0: src = s;   dh = g_sh;  dl = g_sl;  break;
        case 1: src = kin; dh = g_kih; dl = g_kil; break;
        case 2: src = Wq;  dh = g_Wqh; dl = g_Wql; break;
        case 3: src = Wk;  dh = g_Wkh; dl = g_Wkl; break;
        case 4: src = Wv;  dh = g_Wvh; dl = g_Wvl; break;
        case 5: src = Wg;  dh = g_Wgh; dl = g_Wgl; break;
        default: src = Wo; dh = g_Woh; dl = g_Wol; break;
    }
    const int stride = gridDim.x * 256;
    for (int i = blockIdx.x * 256 + threadIdx.x; i < (CS * CS) / 4; i += stride) {
        float4 v = ((const float4*)src)[i];
        uint2 hi, lo; split4(v, &hi, &lo);
        ((uint2*)dh)[i] = hi;
        ((uint2*)dl)[i] = lo;
    }
}

// ====== bf16-split GEMM (templated BN): cp.async 3-stage, 1 barrier/iter ===
#define ASTR 80
#define SA_BYTES (128 * ASTR)

#define EP_F32 0
#define EP_PAIR 1
#define EP_PAIR_BIAS 2
#define EP_F32_SIG 3

template <int BN>
__device__ __forceinline__ void gemm_bf16_body(
    const __nv_bfloat16* __restrict__ Ah, const __nv_bfloat16* __restrict__ Al,
    const __nv_bfloat16* __restrict__ Bh, const __nv_bfloat16* __restrict__ Bl,
    const float* __restrict__ bias, int mode,
    float* __restrict__ Cf, __nv_bfloat16* __restrict__ Ch,
    __nv_bfloat16* __restrict__ Cl, int bm, int bn, uint8_t* dsm)
{
    constexpr int SBB = BN * ASTR;
    constexpr int STG = 2 * SA_BYTES + 2 * SBB;
    constexpr int NF = BN / 16;
    constexpr int GI = BN / 32;
    const uint32_t sb = smem_u32(dsm);

    const int tid = threadIdx.x, wid = tid >> 5, lane = tid & 31;
    const int wm = (wid & 3) * 32, wn = (wid >> 2) * (BN / 2);
    const int lrow = lane & 15, lch = lane >> 4;

    float acc[2][NF][4];
#pragma unroll
    for (int a = 0; a < 2; a++)
#pragma unroll
        for (int b = 0; b < NF; b++)
#pragma unroll
            for (int e = 0; e < 4; e++) acc[a][b][e] = 0.f;

    auto issue = [&](int c, int st) {
        uint32_t stb = sb + st * STG;
#pragma unroll
        for (int i = 0; i < 4; i++) {
            int u = tid + i * 256; int arr = u >> 9; int rem = u & 511;
            int row = rem >> 2, un = rem & 3;
            const __nv_bfloat16* gp = (arr ? Al : Ah) +
                (size_t)(bm + row) * CS + c * 32 + un * 8;
            cpa16(stb + arr * SA_BYTES + row * ASTR + un * 16, gp);
        }
#pragma unroll
        for (int i = 0; i < BN / 32; i++) {
            int u = tid + i * 256; int arr = u / (BN * 4); int rem = u % (BN * 4);
            int row = rem >> 2, un = rem & 3;
            const __nv_bfloat16* gp = (arr ? Bl : Bh) +
                (size_t)(bn + row) * CS + c * 32 + un * 8;
            cpa16(stb + 2 * SA_BYTES + arr * SBB + row * ASTR + un * 16, gp);
        }
    };

    issue(0, 0); cpa_commit();
    issue(1, 1); cpa_commit();

    for (int c = 0; c < 32; c++) {
        if (c < 31) cpa_wait<1>(); else cpa_wait<0>();
        __syncthreads();
        if (c + 2 < 32) { issue(c + 2, (c + 2) % 3); cpa_commit(); }

        const uint32_t stb = sb + (c % 3) * STG;
#pragma unroll
        for (int kh = 0; kh < 2; kh++) {
            uint32_t Af[2][4], Af2[2][4], Bf[GI][4], Bf2[GI][4];
#pragma unroll
            for (int mf = 0; mf < 2; mf++) {
                uint32_t off = (uint32_t)((wm + mf * 16 + lrow) * ASTR + kh * 32 + lch * 16);
                ldsm4(Af[mf],  stb + off);
                ldsm4(Af2[mf], stb + SA_BYTES + off);
            }
#pragma unroll
            for (int gi = 0; gi < GI; gi++) {
                uint32_t off = (uint32_t)((wn + gi * 16 + lrow) * ASTR + kh * 32 + lch * 16);
                ldsm4(Bf[gi],  stb + 2 * SA_BYTES + off);
                ldsm4(Bf2[gi], stb + 2 * SA_BYTES + SBB + off);
            }
#pragma unroll
            for (int mf = 0; mf < 2; mf++)
#pragma unroll
                for (int nf = 0; nf < NF; nf++) {
                    int gi = nf >> 1, s2 = nf & 1;
                    mma_bf16(acc[mf][nf], Af[mf],  Bf[gi][s2],  Bf[gi][s2 + 2]);
                    mma_bf16(acc[mf][nf], Af[mf],  Bf2[gi][s2], Bf2[gi][s2 + 2]);
                    mma_bf16(acc[mf][nf], Af2[mf], Bf[gi][s2],  Bf[gi][s2 + 2]);
                }
        }
    }

#pragma unroll
    for (int mf = 0; mf < 2; mf++)
#pragma unroll
        for (int nf = 0; nf < NF; nf++) {
            int col = bn + wn + nf * 8 + (lane & 3) * 2;
#pragma unroll
            for (int rh = 0; rh < 2; rh++) {
                int row = bm + wm + mf * 16 + (lane >> 2) + rh * 8;
                float v0 = acc[mf][nf][rh * 2 + 0];
                float v1 = acc[mf][nf][rh * 2 + 1];
                if (mode == EP_PAIR_BIAS) { v0 += bias[col]; v1 += bias[col + 1]; }
                if (mode == EP_F32_SIG) {
                    v0 = 1.0f / (1.0f + __expf(-v0));
                    v1 = 1.0f / (1.0f + __expf(-v1));
                }
                if (mode == EP_F32 || mode == EP_F32_SIG) {
                    float2 st2; st2.x = v0; st2.y = v1;
                    *(float2*)(Cf + (size_t)row * CS + col) = st2;
                } else {
                    uint32_t hp, lp; split2(v0, v1, &hp, &lp);
                    *(uint32_t*)(Ch + (size_t)row * CS + col) = hp;
                    *(uint32_t*)(Cl + (size_t)row * CS + col) = lp;
                }
            }
        }
}

#define GEMM_SMEM (3 * (2 * SA_BYTES + 2 * 64 * ASTR))   // 92160 (BN=64, 3-stage)
#define GATED_SMEM (3 * (2 * SA_BYTES + 2 * 32 * ASTR))  // 76800 (BN=32, 3-stage)

// ============ z body (256 threads = two independent 128-thread groups) =====
#define ZG_BYTES (2 * 128 * ASTR + 2 * 16 * 272)   // 29184 per group

__device__ __forceinline__ void z_body256(
    uint8_t* dsm, const float* __restrict__ bias, const float* __restrict__ Wz,
    const float* __restrict__ mask, float* __restrict__ z, size_t bm0)
{
    const int tid = threadIdx.x;
    const int grp = tid >> 7;
    const int gtid = tid & 127;
    const int wid = gtid >> 5, lane = gtid & 31;
    const size_t bm = bm0 + (size_t)grp * 128;
    const int wm = wid * 32;
    const int lrow = lane & 15, lch = lane >> 4;

    uint8_t* base = dsm + grp * ZG_BYTES;
    uint8_t* sAh = base;
    uint8_t* sAl = base + 128 * ASTR;
    uint8_t* sWh = base + 2 * 128 * ASTR;
    uint8_t* sWl = base + 2 * 128 * ASTR + 16 * 272;

#pragma unroll
    for (int i = 0; i < 16; i++) {
        int idx = gtid + i * 128;
        int h = idx >> 7, c = idx & 127;
        float v = Wz[c * NH + h];
        __nv_bfloat16 hb = __float2bfloat16_rn(v);
        *(uint16_t*)(sWh + h * 272 + c * 2) = __bfloat16_as_ushort(hb);
        *(uint16_t*)(sWl + h * 272 + c * 2) =
            __bfloat16_as_ushort(__float2bfloat16_rn(v - __bfloat162float(hb)));
    }

    float acc[2][2][4] = {};
    float4 ra[8];

#define ZLOAD(c) do {                                                          \
    _Pragma("unroll")                                                          \
    for (int i = 0; i < 8; i++) {                                              \
        int slot = gtid + i * 128; int row = slot >> 3, qq = slot & 7;         \
        ra[i] = *(const float4*)(bias + (bm + row) * CZ + (c) * 32 + qq * 4);  \
    } } while (0)

    ZLOAD(0);
    for (int c = 0; c < 4; c++) {
        __syncthreads();
#pragma unroll
        for (int i = 0; i < 8; i++) {
            int slot = gtid + i * 128; int row = slot >> 3, qq = slot & 7;
            uint2 hi, lo; split4(ra[i], &hi, &lo);
            *(uint2*)(sAh + row * ASTR + qq * 8) = hi;
            *(uint2*)(sAl + row * ASTR + qq * 8) = lo;
        }
        __syncthreads();
        if (c < 3) ZLOAD(c + 1);

#pragma unroll
        for (int kh = 0; kh < 2; kh++) {
            uint32_t Wh[4], Wl[4];
            uint32_t woff = (uint32_t)(lrow * 272 + c * 64 + kh * 32 + lch * 16);
            ldsm4(Wh, smem_u32(sWh) + woff);
            ldsm4(Wl, smem_u32(sWl) + woff);
#pragma unroll
            for (int mf = 0; mf < 2; mf++) {
                uint32_t Ah[4], Al[4];
                uint32_t off = (uint32_t)((wm + mf * 16 + lrow) * ASTR + kh * 32 + lch * 16);
                ldsm4(Ah, smem_u32(sAh) + off);
                ldsm4(Al, smem_u32(sAl) + off);
#pragma unroll
                for (int nf = 0; nf < 2; nf++) {
                    mma_bf16(acc[mf][nf], Ah, Wh[nf], Wh[nf + 2]);
                    mma_bf16(acc[mf][nf], Ah, Wl[nf], Wl[nf + 2]);
                    mma_bf16(acc[mf][nf], Al, Wh[nf], Wh[nf + 2]);
                }
            }
        }
    }
#undef ZLOAD

#pragma unroll
    for (int mf = 0; mf < 2; mf++)
#pragma unroll
        for (int rh = 0; rh < 2; rh++) {
            size_t m = bm + wm + mf * 16 + (lane >> 2) + rh * 8;
            float mterm = (1.0f - mask[m & (NJ - 1)]) * (-1000000.0f);
#pragma unroll
            for (int nf = 0; nf < 2; nf++) {
                int h0 = nf * 8 + (lane & 3) * 2;
                z[(size_t)h0 * ((size_t)NI * NJ) + m]       = acc[mf][nf][rh * 2 + 0] + mterm;
                z[(size_t)(h0 + 1) * ((size_t)NI * NJ) + m] = acc[mf][nf][rh * 2 + 1] + mterm;
            }
        }
}

// ============ fused proj + z, INTERLEAVED so every wave mixes both =========
// t % 9 == 0  -> projection tile (512 blocks, tensor-bound)
// otherwise   -> z block (4096 blocks, DRAM-bound)
__global__ __launch_bounds__(256, 2) void fused_pz(
    const float* __restrict__ bq, const float* __restrict__ bias,
    const float* __restrict__ Wz, const float* __restrict__ mask,
    float* __restrict__ z)
{
    extern __shared__ __align__(16) uint8_t dsm[];
    const int t = blockIdx.x;
    if (t % 9 == 0) {
        const int p = t / 9;                 // 0..511
        const int pid = p >> 7, rem = p & 127;
        const int bn = (rem & 15) * 64, bm = (rem >> 4) * 128;
        switch (pid) {
            case 0:
                gemm_bf16_body<64>(g_sh, g_sl, g_Wqh, g_Wql, bq, EP_PAIR_BIAS,
                                   nullptr, g_qh, g_ql, bm, bn, dsm);
                break;
            case 1:
                gemm_bf16_body<64>(g_kih, g_kil, g_Wkh, g_Wkl, nullptr, EP_PAIR,
                                   nullptr, g_kh, g_kl, bm, bn, dsm);
                break;
            case 2:
                gemm_bf16_body<64>(g_kih, g_kil, g_Wvh, g_Wvl, nullptr, EP_PAIR,
                                   nullptr, g_vh, g_vl, bm, bn, dsm);
                break;
            default:
                gemm_bf16_body<64>(g_sh, g_sl, g_Wgh, g_Wgl, nullptr, EP_F32_SIG,
                                   g_gt, nullptr, nullptr, bm, bn, dsm);
                break;
        }
    } else {
        const int zi = t - 1 - t / 9;        // 0..4095
        z_body256(dsm, bias, Wz, mask, z, (size_t)zi * 256);
    }
}

// ============ gated output projection: 128x32 tiles, 256 blocks ============
__global__ __launch_bounds__(256, 2) void mma_gated(float* __restrict__ out)
{
    extern __shared__ __align__(16) uint8_t dsm[];
    gemm_bf16_body<32>(g_goh, g_gol, g_Woh, g_Wol, nullptr, EP_F32,
                       out, nullptr, nullptr, blockIdx.y * 128, blockIdx.x * 32,
                       dsm);
}

// ============ flash attention: block = 64 i x 1 head, 4 warps ==============
#define FST 144
#define RG_B (64 * FST)
#define STG_B (4 * RG_B)
#define AT_SMEM (2 * STG_B)

__global__ __launch_bounds__(128, 2) void attn_flash(const float* __restrict__ z)
{
    extern __shared__ __align__(16) uint8_t dsm[];
    const uint32_t sb = smem_u32(dsm);
    const int tid = threadIdx.x, wid = tid >> 5, lane = tid & 31;
    const int i0 = blockIdx.x * 64;
    const int h  = blockIdx.y;
    const int lrow = lane & 15, lch = lane >> 4;
    const int r   = lane >> 2;
    const int cq  = (lane & 3) * 2;

    for (int i = tid; i < 1024; i += 128) {
        int un = i & 7, row = (i >> 3) & 63, rg = i >> 9;
        const __nv_bfloat16* src = (rg ? g_ql : g_qh) +
            (size_t)(i0 + row) * CS + h * ND + un * 8;
        cpa16(sb + rg * RG_B + row * FST + un * 16, src);
    }
    cpa_commit(); cpa_wait<0>(); __syncthreads();
    uint32_t qh[4][4], ql[4][4];
#pragma unroll
    for (int kh = 0; kh < 4; kh++) {
        uint32_t off = (uint32_t)((wid * 16 + lrow) * FST + kh * 32 + lch * 16);
        ldsm4(qh[kh], sb + off);
        ldsm4(ql[kh], sb + RG_B + off);
    }
    __syncthreads();

    float accO[8][4] = {};
    float m0 = -1e30f, m1 = -1e30f, l0 = 0.f, l1 = 0.f;

#define KVISSUE(c) do {                                                        \
    uint32_t stb_ = sb + ((c) & 1) * STG_B;                                    \
    for (int i = tid; i < 2048; i += 128) {                                    \
        int un = i & 7, row = (i >> 3) & 63, rg = i >> 9;                      \
        const __nv_bfloat16* src;                                              \
        switch (rg) { case 0: src = g_kh; break; case 1: src = g_kl; break;    \
                      case 2: src = g_vh; break; default: src = g_vl; }        \
        src += (size_t)((c) * 64 + row) * CS + h * ND + un * 8;                \
        cpa16(stb_ + rg * RG_B + row * FST + un * 16, src);                    \
    } } while (0)

    KVISSUE(0); cpa_commit();
    const float* zb0 = z + (size_t)h * ((size_t)NI * NJ) +
                       (size_t)(i0 + wid * 16 + r) * NJ;
    const float* zb1 = zb0 + 8 * NJ;

    for (int c = 0; c < 16; c++) {
        if (c < 15) { KVISSUE(c + 1); cpa_commit(); cpa_wait<1>(); }
        else cpa_wait<0>();
        __syncthreads();
        const uint32_t stb = sb + (c & 1) * STG_B;

        float accS[8][4] = {};
#pragma unroll
        for (int kh = 0; kh < 4; kh++) {
#pragma unroll
            for (int jg = 0; jg < 4; jg++) {
                uint32_t off = (uint32_t)((jg * 16 + lrow) * FST + kh * 32 + lch * 16);
                uint32_t KH[4], KL[4];
                ldsm4(KH, stb + off);
                ldsm4(KL, stb + RG_B + off);
                mma_bf16(accS[jg * 2 + 0], qh[kh], KH[0], KH[2]);
                mma_bf16(accS[jg * 2 + 1], qh[kh], KH[1], KH[3]);
                mma_bf16(accS[jg * 2 + 0], qh[kh], KL[0], KL[2]);
                mma_bf16(accS[jg * 2 + 1], qh[kh], KL[1], KL[3]);
                mma_bf16(accS[jg * 2 + 0], ql[kh], KH[0], KH[2]);
                mma_bf16(accS[jg * 2 + 1], ql[kh], KH[1], KH[3]);
            }
        }

        float mc0 = -1e30f, mc1 = -1e30f;
#pragma unroll
        for (int nf = 0; nf < 8; nf++) {
            int col = c * 64 + nf * 8 + cq;
            float2 za = *(const float2*)(zb0 + col);
            float2 zc = *(const float2*)(zb1 + col);
            accS[nf][0] = fmaf(accS[nf][0], 0.125f, za.x);
            accS[nf][1] = fmaf(accS[nf][1], 0.125f, za.y);
            accS[nf][2] = fmaf(accS[nf][2], 0.125f, zc.x);
            accS[nf][3] = fmaf(accS[nf][3], 0.125f, zc.y);
            mc0 = fmaxf(mc0, fmaxf(accS[nf][0], accS[nf][1]));
            mc1 = fmaxf(mc1, fmaxf(accS[nf][2], accS[nf][3]));
        }
        mc0 = fmaxf(mc0, __shfl_xor_sync(0xffffffffu, mc0, 1));
        mc0 = fmaxf(mc0, __shfl_xor_sync(0xffffffffu, mc0, 2));
        mc1 = fmaxf(mc1, __shfl_xor_sync(0xffffffffu, mc1, 1));
        mc1 = fmaxf(mc1, __shfl_xor_sync(0xffffffffu, mc1, 2));
        float nm0 = fmaxf(m0, mc0), nm1 = fmaxf(m1, mc1);
        float sc0 = __expf(m0 - nm0), sc1 = __expf(m1 - nm1);
        m0 = nm0; m1 = nm1;
        l0 *= sc0; l1 *= sc1;
#pragma unroll
        for (int nf = 0; nf < 8; nf++) {
            accO[nf][0] *= sc0; accO[nf][1] *= sc0;
            accO[nf][2] *= sc1; accO[nf][3] *= sc1;
        }

        uint32_t Ph[4][4], Pl[4][4];
#pragma unroll
        for (int kg = 0; kg < 4; kg++) {
#pragma unroll
            for (int half = 0; half < 2; half++) {
                int nf = kg * 2 + half;
                float p0 = __expf(accS[nf][0] - m0);
                float p1 = __expf(accS[nf][1] - m0);
                float p2 = __expf(accS[nf][2] - m1);
                float p3 = __expf(accS[nf][3] - m1);
                l0 += p0 + p1; l1 += p2 + p3;
                __nv_bfloat16 b0 = __float2bfloat16_rn(p0);
                __nv_bfloat16 b1 = __float2bfloat16_rn(p1);
                __nv_bfloat16 b2 = __float2bfloat16_rn(p2);
                __nv_bfloat16 b3 = __float2bfloat16_rn(p3);
                Ph[kg][half * 2 + 0] = pack2(b0, b1);
                Ph[kg][half * 2 + 1] = pack2(b2, b3);
                Pl[kg][half * 2 + 0] =
                    pack2(__float2bfloat16_rn(p0 - __bfloat162float(b0)),
                          __float2bfloat16_rn(p1 - __bfloat162float(b1)));
                Pl[kg][half * 2 + 1] =
                    pack2(__float2bfloat16_rn(p2 - __bfloat162float(b2)),
                          __float2bfloat16_rn(p3 - __bfloat162float(b3)));
            }
        }

#pragma unroll
        for (int kg = 0; kg < 4; kg++) {
#pragma unroll
            for (int ng = 0; ng < 4; ng++) {
                uint32_t voff = (uint32_t)((kg * 16 + lrow) * FST + ng * 32 + lch * 16);
                uint32_t VH[4], VL[4];
                ldsm4t(VH, stb + 2 * RG_B + voff);
                ldsm4t(VL, stb + 3 * RG_B + voff);
                mma_bf16(accO[ng * 2 + 0], Ph[kg], VH[0], VH[1]);
                mma_bf16(accO[ng * 2 + 1], Ph[kg], VH[2], VH[3]);
                mma_bf16(accO[ng * 2 + 0], Ph[kg], VL[0], VL[1]);
                mma_bf16(accO[ng * 2 + 1], Ph[kg], VL[2], VL[3]);
                mma_bf16(accO[ng * 2 + 0], Pl[kg], VH[0], VH[1]);
                mma_bf16(accO[ng * 2 + 1], Pl[kg], VH[2], VH[3]);
            }
        }
        __syncthreads();
    }
#undef KVISSUE

    l0 += __shfl_xor_sync(0xffffffffu, l0, 1);
    l0 += __shfl_xor_sync(0xffffffffu, l0, 2);
    l1 += __shfl_xor_sync(0xffffffffu, l1, 1);
    l1 += __shfl_xor_sync(0xffffffffu, l1, 2);
    float il0 = 1.0f / l0, il1 = 1.0f / l1;

    const int row0 = i0 + wid * 16 + r, row1 = row0 + 8;
#pragma unroll
    for (int nf = 0; nf < 8; nf++) {
        int col = h * ND + nf * 8 + cq;
        float2 ga = *(const float2*)(g_gt + (size_t)row0 * CS + col);
        float2 gb = *(const float2*)(g_gt + (size_t)row1 * CS + col);
        uint32_t hp, lp;
        split2(accO[nf][0] * il0 * ga.x, accO[nf][1] * il0 * ga.y, &hp, &lp);
        *(uint32_t*)(g_goh + (size_t)row0 * CS + col) = hp;
        *(uint32_t*)(g_gol + (size_t)row0 * CS + col) = lp;
        split2(accO[nf][2] * il1 * gb.x, accO[nf][3] * il1 * gb.y, &hp, &lp);
        *(uint32_t*)(g_goh + (size_t)row1 * CS + col) = hp;
        *(uint32_t*)(g_gol + (size_t)row1 * CS + col) = lp;
    }
}

// ---------------------------------------------------------------------------
extern "C" void kernel_launch(void* const* d_in, const int* in_sizes, int n_in,
                              void* d_out, int out_size)
{
    (void)in_sizes; (void)n_in; (void)out_size;
    const float* s    = (const float*)d_in[0];
    const float* k_in = (const float*)d_in[1];
    const float* mask = (const float*)d_in[2];
    const float* bias = (const float*)d_in[3];
    const float* bq   = (const float*)d_in[5];
    const float* Wz   = (const float*)d_in[10];
    float* out = (float*)d_out;

    float* z;
    cudaGetSymbolAddress((void**)&z, g_z);

    cudaFuncSetAttribute(fused_pz,   cudaFuncAttributeMaxDynamicSharedMemorySize,
                         GEMM_SMEM);
    cudaFuncSetAttribute(mma_gated,  cudaFuncAttributeMaxDynamicSharedMemorySize,
                         GATED_SMEM);
    cudaFuncSetAttribute(attn_flash, cudaFuncAttributeMaxDynamicSharedMemorySize,
                         AT_SMEM);

    // split inputs + weights to bf16 hi/lo once
    preconv<<<dim3(128, 7), 256>>>(s, k_in, (const float*)d_in[4],
                                   (const float*)d_in[6], (const float*)d_in[7],
                                   (const float*)d_in[8], (const float*)d_in[9]);
    // projections + z projection, interleaved for real co-scheduling
    fused_pz<<<512 + 4096, 256, GEMM_SMEM>>>(bq, bias, Wz, mask, z);
    // flash attention (online softmax, register-resident P)
    attn_flash<<<dim3(NI / 64, NH), 128, AT_SMEM>>>(z);
    // gated output projection (256 blocks, 128x32 tiles, 3-stage)
    mma_gated<<<dim3(32, 8), 256, GATED_SMEM>>>(out);
}

// round 13
// speedup vs baseline: 1.1124x; 1.1124x over previous
#include <cuda_runtime.h>
#include <cuda_bf16.h>
#include <stdint.h>
#include <math.h>

#define CS 1024
#define NI 1024
#define NJ 1024
#define NH 16
#define ND 64
#define CZ 128

// ---------------- scratch (device globals; no allocation allowed) ----------
__device__ float g_gt[NI * CS];                       // sigmoid gate (fp32)
__device__ float g_z[(size_t)NH * NI * NJ];           // pair bias [h][i*NJ+j]
__device__ __nv_bfloat16 g_sh[NI * CS],  g_sl[NI * CS];
__device__ __nv_bfloat16 g_kih[NJ * CS], g_kil[NJ * CS];
__device__ __nv_bfloat16 g_Wqh[CS * CS], g_Wql[CS * CS];
__device__ __nv_bfloat16 g_Wkh[CS * CS], g_Wkl[CS * CS];
__device__ __nv_bfloat16 g_Wvh[CS * CS], g_Wvl[CS * CS];
__device__ __nv_bfloat16 g_Wgh[CS * CS], g_Wgl[CS * CS];
__device__ __nv_bfloat16 g_Woh[CS * CS], g_Wol[CS * CS];
__device__ __nv_bfloat16 g_qh[NI * CS],  g_ql[NI * CS];
__device__ __nv_bfloat16 g_kh[NJ * CS],  g_kl[NJ * CS];
__device__ __nv_bfloat16 g_vh[NJ * CS],  g_vl[NJ * CS];
__device__ __nv_bfloat16 g_goh[NI * CS], g_gol[NI * CS];

// ===================== mma.sync / cp.async helpers =========================
__device__ __forceinline__ uint32_t smem_u32(const void* p) {
    uint32_t r;
    asm("{ .reg .u64 t; cvta.to.shared.u64 t, %1; cvt.u32.u64 %0, t; }"
        : "=r"(r) : "l"(p));
    return r;
}
__device__ __forceinline__ void ldsm4(uint32_t* r, uint32_t a) {
    asm volatile("ldmatrix.sync.aligned.m8n8.x4.shared.b16 {%0,%1,%2,%3}, [%4];"
                 : "=r"(r[0]), "=r"(r[1]), "=r"(r[2]), "=r"(r[3]) : "r"(a));
}
__device__ __forceinline__ void ldsm4t(uint32_t* r, uint32_t a) {
    asm volatile("ldmatrix.sync.aligned.m8n8.x4.trans.shared.b16 {%0,%1,%2,%3}, [%4];"
                 : "=r"(r[0]), "=r"(r[1]), "=r"(r[2]), "=r"(r[3]) : "r"(a));
}
__device__ __forceinline__ void mma_bf16(float* d, const uint32_t* a,
                                         uint32_t b0, uint32_t b1) {
    asm volatile(
        "mma.sync.aligned.m16n8k16.row.col.f32.bf16.bf16.f32 "
        "{%0,%1,%2,%3}, {%4,%5,%6,%7}, {%8,%9}, {%0,%1,%2,%3};"
        : "+f"(d[0]), "+f"(d[1]), "+f"(d[2]), "+f"(d[3])
        : "r"(a[0]), "r"(a[1]), "r"(a[2]), "r"(a[3]), "r"(b0), "r"(b1));
}
__device__ __forceinline__ void cpa16(uint32_t s, const void* g) {
    asm volatile("cp.async.cg.shared.global [%0], [%1], 16;" :: "r"(s), "l"(g));
}
__device__ __forceinline__ void cpa_commit() {
    asm volatile("cp.async.commit_group;");
}
template <int N> __device__ __forceinline__ void cpa_wait() {
    asm volatile("cp.async.wait_group %0;" :: "n"(N));
}
__device__ __forceinline__ uint32_t pack2(__nv_bfloat16 a, __nv_bfloat16 b) {
    return (uint32_t)__bfloat16_as_ushort(a) |
           ((uint32_t)__bfloat16_as_ushort(b) << 16);
}
__device__ __forceinline__ void split4(float4 v, uint2* hi, uint2* lo) {
    __nv_bfloat16 h0 = __float2bfloat16_rn(v.x);
    __nv_bfloat16 h1 = __float2bfloat16_rn(v.y);
    __nv_bfloat16 h2 = __float2bfloat16_rn(v.z);
    __nv_bfloat16 h3 = __float2bfloat16_rn(v.w);
    hi->x = pack2(h0, h1); hi->y = pack2(h2, h3);
    lo->x = pack2(__float2bfloat16_rn(v.x - __bfloat162float(h0)),
                  __float2bfloat16_rn(v.y - __bfloat162float(h1)));
    lo->y = pack2(__float2bfloat16_rn(v.z - __bfloat162float(h2)),
                  __float2bfloat16_rn(v.w - __bfloat162float(h3)));
}
__device__ __forceinline__ void split2(float v0, float v1,
                                       uint32_t* hp, uint32_t* lp) {
    __nv_bfloat16 h0 = __float2bfloat16_rn(v0);
    __nv_bfloat16 h1 = __float2bfloat16_rn(v1);
    *hp = pack2(h0, h1);
    *lp = pack2(__float2bfloat16_rn(v0 - __bfloat162float(h0)),
                __float2bfloat16_rn(v1 - __bfloat162float(h1)));
}

// ============ preconvert: fp32 -> bf16 hi/lo for 7 matrices (1M each) ======
__global__ __launch_bounds__(256) void preconv(
    const float* __restrict__ s, const float* __restrict__ kin,
    const float* __restrict__ Wq, const float* __restrict__ Wk,
    const float* __restrict__ Wv, const float* __restrict__ Wg,
    const float* __restrict__ Wo)
{
    const float* src; __nv_bfloat16 *dh, *dl;
    switch (blockIdx.y) {
        case 0: src = s;   dh = g_sh;  dl = g_sl;  break;
        case 1: src = kin; dh = g_kih; dl = g_kil; break;
        case 2: src = Wq;  dh = g_Wqh; dl = g_Wql; break;
        case 3: src = Wk;  dh = g_Wkh; dl = g_Wkl; break;
        case 4: src = Wv;  dh = g_Wvh; dl = g_Wvl; break;
        case 5: src = Wg;  dh = g_Wgh; dl = g_Wgl; break;
        default: src = Wo; dh = g_Woh; dl = g_Wol; break;
    }
    const int stride = gridDim.x * 256;
    for (int i = blockIdx.x * 256 + threadIdx.x; i < (CS * CS) / 4; i += stride) {
        float4 v = ((const float4*)src)[i];
        uint2 hi, lo; split4(v, &hi, &lo);
        ((uint2*)dh)[i] = hi;
        ((uint2*)dl)[i] = lo;
    }
}

// ====== bf16-split GEMM (templated BN): cp.async 3-stage, 1 barrier/iter ===
#define ASTR 80
#define SA_BYTES (128 * ASTR)

#define EP_F32 0
#define EP_PAIR 1
#define EP_PAIR_BIAS 2
#define EP_F32_SIG 3

template <int BN>
__device__ __forceinline__ void gemm_bf16_body(
    const __nv_bfloat16* __restrict__ Ah, const __nv_bfloat16* __restrict__ Al,
    const __nv_bfloat16* __restrict__ Bh, const __nv_bfloat16* __restrict__ Bl,
    const float* __restrict__ bias, int mode,
    float* __restrict__ Cf, __nv_bfloat16* __restrict__ Ch,
    __nv_bfloat16* __restrict__ Cl, int bm, int bn, uint8_t* dsm)
{
    constexpr int SBB = BN * ASTR;
    constexpr int STG = 2 * SA_BYTES + 2 * SBB;
    constexpr int NF = BN / 16;
    constexpr int GI = BN / 32;
    const uint32_t sb = smem_u32(dsm);

    const int tid = threadIdx.x, wid = tid >> 5, lane = tid & 31;
    const int wm = (wid & 3) * 32, wn = (wid >> 2) * (BN / 2);
    const int lrow = lane & 15, lch = lane >> 4;

    float acc[2][NF][4];
#pragma unroll
    for (int a = 0; a < 2; a++)
#pragma unroll
        for (int b = 0; b < NF; b++)
#pragma unroll
            for (int e = 0; e < 4; e++) acc[a][b][e] = 0.f;

    auto issue = [&](int c, int st) {
        uint32_t stb = sb + st * STG;
#pragma unroll
        for (int i = 0; i < 4; i++) {
            int u = tid + i * 256; int arr = u >> 9; int rem = u & 511;
            int row = rem >> 2, un = rem & 3;
            const __nv_bfloat16* gp = (arr ? Al : Ah) +
                (size_t)(bm + row) * CS + c * 32 + un * 8;
            cpa16(stb + arr * SA_BYTES + row * ASTR + un * 16, gp);
        }
#pragma unroll
        for (int i = 0; i < BN / 32; i++) {
            int u = tid + i * 256; int arr = u / (BN * 4); int rem = u % (BN * 4);
            int row = rem >> 2, un = rem & 3;
            const __nv_bfloat16* gp = (arr ? Bl : Bh) +
                (size_t)(bn + row) * CS + c * 32 + un * 8;
            cpa16(stb + 2 * SA_BYTES + arr * SBB + row * ASTR + un * 16, gp);
        }
    };

    issue(0, 0); cpa_commit();
    issue(1, 1); cpa_commit();

    for (int c = 0; c < 32; c++) {
        if (c < 31) cpa_wait<1>(); else cpa_wait<0>();
        __syncthreads();
        if (c + 2 < 32) { issue(c + 2, (c + 2) % 3); cpa_commit(); }

        const uint32_t stb = sb + (c % 3) * STG;
#pragma unroll
        for (int kh = 0; kh < 2; kh++) {
            uint32_t Af[2][4], Af2[2][4], Bf[GI][4], Bf2[GI][4];
#pragma unroll
            for (int mf = 0; mf < 2; mf++) {
                uint32_t off = (uint32_t)((wm + mf * 16 + lrow) * ASTR + kh * 32 + lch * 16);
                ldsm4(Af[mf],  stb + off);
                ldsm4(Af2[mf], stb + SA_BYTES + off);
            }
#pragma unroll
            for (int gi = 0; gi < GI; gi++) {
                uint32_t off = (uint32_t)((wn + gi * 16 + lrow) * ASTR + kh * 32 + lch * 16);
                ldsm4(Bf[gi],  stb + 2 * SA_BYTES + off);
                ldsm4(Bf2[gi], stb + 2 * SA_BYTES + SBB + off);
            }
#pragma unroll
            for (int mf = 0; mf < 2; mf++)
#pragma unroll
                for (int nf = 0; nf < NF; nf++) {
                    int gi = nf >> 1, s2 = nf & 1;
                    mma_bf16(acc[mf][nf], Af[mf],  Bf[gi][s2],  Bf[gi][s2 + 2]);
                    mma_bf16(acc[mf][nf], Af[mf],  Bf2[gi][s2], Bf2[gi][s2 + 2]);
                    mma_bf16(acc[mf][nf], Af2[mf], Bf[gi][s2],  Bf[gi][s2 + 2]);
                }
        }
    }

#pragma unroll
    for (int mf = 0; mf < 2; mf++)
#pragma unroll
        for (int nf = 0; nf < NF; nf++) {
            int col = bn + wn + nf * 8 + (lane & 3) * 2;
#pragma unroll
            for (int rh = 0; rh < 2; rh++) {
                int row = bm + wm + mf * 16 + (lane >> 2) + rh * 8;
                float v0 = acc[mf][nf][rh * 2 + 0];
                float v1 = acc[mf][nf][rh * 2 + 1];
                if (mode == EP_PAIR_BIAS) { v0 += bias[col]; v1 += bias[col + 1]; }
                if (mode == EP_F32_SIG) {
                    v0 = 1.0f / (1.0f + __expf(-v0));
                    v1 = 1.0f / (1.0f + __expf(-v1));
                }
                if (mode == EP_F32 || mode == EP_F32_SIG) {
                    float2 st2; st2.x = v0; st2.y = v1;
                    *(float2*)(Cf + (size_t)row * CS + col) = st2;
                } else {
                    uint32_t hp, lp; split2(v0, v1, &hp, &lp);
                    *(uint32_t*)(Ch + (size_t)row * CS + col) = hp;
                    *(uint32_t*)(Cl + (size_t)row * CS + col) = lp;
                }
            }
        }
}

#define GEMM_SMEM (3 * (2 * SA_BYTES + 2 * 64 * ASTR))   // 92160 (BN=64, 3-stage)
#define GATED_SMEM (3 * (2 * SA_BYTES + 2 * 32 * ASTR))  // 76800 (BN=32, 3-stage)

// ============ z body (256 threads = two independent 128-thread groups) =====
#define ZG_BYTES (2 * 128 * ASTR + 2 * 16 * 272)   // 29184 per group

__device__ __forceinline__ void z_body256(
    uint8_t* dsm, const float* __restrict__ bias, const float* __restrict__ Wz,
    const float* __restrict__ mask, float* __restrict__ z, size_t bm0)
{
    const int tid = threadIdx.x;
    const int grp = tid >> 7;
    const int gtid = tid & 127;
    const int wid = gtid >> 5, lane = gtid & 31;
    const size_t bm = bm0 + (size_t)grp * 128;
    const int wm = wid * 32;
    const int lrow = lane & 15, lch = lane >> 4;

    uint8_t* base = dsm + grp * ZG_BYTES;
    uint8_t* sAh = base;
    uint8_t* sAl = base + 128 * ASTR;
    uint8_t* sWh = base + 2 * 128 * ASTR;
    uint8_t* sWl = base + 2 * 128 * ASTR + 16 * 272;

#pragma unroll
    for (int i = 0; i < 16; i++) {
        int idx = gtid + i * 128;
        int h = idx >> 7, c = idx & 127;
        float v = Wz[c * NH + h];
        __nv_bfloat16 hb = __float2bfloat16_rn(v);
        *(uint16_t*)(sWh + h * 272 + c * 2) = __bfloat16_as_ushort(hb);
        *(uint16_t*)(sWl + h * 272 + c * 2) =
            __bfloat16_as_ushort(__float2bfloat16_rn(v - __bfloat162float(hb)));
    }

    float acc[2][2][4] = {};
    float4 ra[8];

#define ZLOAD(c) do {                                                          \
    _Pragma("unroll")                                                          \
    for (int i = 0; i < 8; i++) {                                              \
        int slot = gtid + i * 128; int row = slot >> 3, qq = slot & 7;         \
        ra[i] = *(const float4*)(bias + (bm + row) * CZ + (c) * 32 + qq * 4);  \
    } } while (0)

    ZLOAD(0);
    for (int c = 0; c < 4; c++) {
        __syncthreads();
#pragma unroll
        for (int i = 0; i < 8; i++) {
            int slot = gtid + i * 128; int row = slot >> 3, qq = slot & 7;
            uint2 hi, lo; split4(ra[i], &hi, &lo);
            *(uint2*)(sAh + row * ASTR + qq * 8) = hi;
            *(uint2*)(sAl + row * ASTR + qq * 8) = lo;
        }
        __syncthreads();
        if (c < 3) ZLOAD(c + 1);

#pragma unroll
        for (int kh = 0; kh < 2; kh++) {
            uint32_t Wh[4], Wl[4];
            uint32_t woff = (uint32_t)(lrow * 272 + c * 64 + kh * 32 + lch * 16);
            ldsm4(Wh, smem_u32(sWh) + woff);
            ldsm4(Wl, smem_u32(sWl) + woff);
#pragma unroll
            for (int mf = 0; mf < 2; mf++) {
                uint32_t Ah[4], Al[4];
                uint32_t off = (uint32_t)((wm + mf * 16 + lrow) * ASTR + kh * 32 + lch * 16);
                ldsm4(Ah, smem_u32(sAh) + off);
                ldsm4(Al, smem_u32(sAl) + off);
#pragma unroll
                for (int nf = 0; nf < 2; nf++) {
                    mma_bf16(acc[mf][nf], Ah, Wh[nf], Wh[nf + 2]);
                    mma_bf16(acc[mf][nf], Ah, Wl[nf], Wl[nf + 2]);
                    mma_bf16(acc[mf][nf], Al, Wh[nf], Wh[nf + 2]);
                }
            }
        }
    }
#undef ZLOAD

#pragma unroll
    for (int mf = 0; mf < 2; mf++)
#pragma unroll
        for (int rh = 0; rh < 2; rh++) {
            size_t m = bm + wm + mf * 16 + (lane >> 2) + rh * 8;
            float mterm = (1.0f - mask[m & (NJ - 1)]) * (-1000000.0f);
#pragma unroll
            for (int nf = 0; nf < 2; nf++) {
                int h0 = nf * 8 + (lane & 3) * 2;
                z[(size_t)h0 * ((size_t)NI * NJ) + m]       = acc[mf][nf][rh * 2 + 0] + mterm;
                z[(size_t)(h0 + 1) * ((size_t)NI * NJ) + m] = acc[mf][nf][rh * 2 + 1] + mterm;
            }
        }
}

// ============ fused proj + z (concatenated order — R11 mapping) ============
__global__ __launch_bounds__(256, 2) void fused_pz(
    const float* __restrict__ bq, const float* __restrict__ bias,
    const float* __restrict__ Wz, const float* __restrict__ mask,
    float* __restrict__ z)
{
    extern __shared__ __align__(16) uint8_t dsm[];
    const int t = blockIdx.x;
    if (t < 512) {
        const int pid = t >> 7, rem = t & 127;
        const int bn = (rem & 15) * 64, bm = (rem >> 4) * 128;
        switch (pid) {
            case 0:
                gemm_bf16_body<64>(g_sh, g_sl, g_Wqh, g_Wql, bq, EP_PAIR_BIAS,
                                   nullptr, g_qh, g_ql, bm, bn, dsm);
                break;
            case 1:
                gemm_bf16_body<64>(g_kih, g_kil, g_Wkh, g_Wkl, nullptr, EP_PAIR,
                                   nullptr, g_kh, g_kl, bm, bn, dsm);
                break;
            case 2:
                gemm_bf16_body<64>(g_kih, g_kil, g_Wvh, g_Wvl, nullptr, EP_PAIR,
                                   nullptr, g_vh, g_vl, bm, bn, dsm);
                break;
            default:
                gemm_bf16_body<64>(g_sh, g_sl, g_Wgh, g_Wgl, nullptr, EP_F32_SIG,
                                   g_gt, nullptr, nullptr, bm, bn, dsm);
                break;
        }
    } else {
        z_body256(dsm, bias, Wz, mask, z, (size_t)(t - 512) * 256);
    }
}

// ============ gated output projection: 128x32 tiles, 256 blocks ============
__global__ __launch_bounds__(256, 2) void mma_gated(float* __restrict__ out)
{
    extern __shared__ __align__(16) uint8_t dsm[];
    gemm_bf16_body<32>(g_goh, g_gol, g_Woh, g_Wol, nullptr, EP_F32,
                       out, nullptr, nullptr, blockIdx.y * 128, blockIdx.x * 32,
                       dsm);
}

// ============ flash attention: block = 64 i x 1 head, 4 warps ==============
// z now staged through smem via cp.async (same commit group as K/V).
#define FST 144
#define RG_B (64 * FST)                  // 9216
#define ZST 272                          // z row stride bytes (68 floats)
#define ZRG (64 * ZST)                   // 17408
#define STG_B (4 * RG_B + ZRG)           // 54272
#define AT_SMEM (2 * STG_B)              // 108544

__global__ __launch_bounds__(128, 2) void attn_flash(const float* __restrict__ z)
{
    extern __shared__ __align__(16) uint8_t dsm[];
    const uint32_t sb = smem_u32(dsm);
    const int tid = threadIdx.x, wid = tid >> 5, lane = tid & 31;
    const int i0 = blockIdx.x * 64;
    const int h  = blockIdx.y;
    const int lrow = lane & 15, lch = lane >> 4;
    const int r   = lane >> 2;
    const int cq  = (lane & 3) * 2;
    const float* zh = z + (size_t)h * ((size_t)NI * NJ);

    // ---- Q (64x64 hi/lo) via cp.async into stage0, ldsm to registers ----
    for (int i = tid; i < 1024; i += 128) {
        int un = i & 7, row = (i >> 3) & 63, rg = i >> 9;
        const __nv_bfloat16* src = (rg ? g_ql : g_qh) +
            (size_t)(i0 + row) * CS + h * ND + un * 8;
        cpa16(sb + rg * RG_B + row * FST + un * 16, src);
    }
    cpa_commit(); cpa_wait<0>(); __syncthreads();
    uint32_t qh[4][4], ql[4][4];
#pragma unroll
    for (int kh = 0; kh < 4; kh++) {
        uint32_t off = (uint32_t)((wid * 16 + lrow) * FST + kh * 32 + lch * 16);
        ldsm4(qh[kh], sb + off);
        ldsm4(ql[kh], sb + RG_B + off);
    }
    __syncthreads();

    float accO[8][4] = {};
    float m0 = -1e30f, m1 = -1e30f, l0 = 0.f, l1 = 0.f;

#define KVISSUE(c) do {                                                        \
    uint32_t stb_ = sb + ((c) & 1) * STG_B;                                    \
    for (int i = tid; i < 2048; i += 128) {                                    \
        int un = i & 7, row = (i >> 3) & 63, rg = i >> 9;                      \
        const __nv_bfloat16* src;                                              \
        switch (rg) { case 0: src = g_kh; break; case 1: src = g_kl; break;    \
                      case 2: src = g_vh; break; default: src = g_vl; }        \
        src += (size_t)((c) * 64 + row) * CS + h * ND + un * 8;                \
        cpa16(stb_ + rg * RG_B + row * FST + un * 16, src);                    \
    }                                                                          \
    for (int i = tid; i < 1024; i += 128) {                                    \
        int row = i >> 4, un = i & 15;                                         \
        const float* zsrc = zh + (size_t)(i0 + row) * NJ + (c) * 64 + un * 4;  \
        cpa16(stb_ + 4 * RG_B + row * ZST + un * 16, zsrc);                    \
    } } while (0)

    KVISSUE(0); cpa_commit();

    for (int c = 0; c < 16; c++) {
        if (c < 15) { KVISSUE(c + 1); cpa_commit(); cpa_wait<1>(); }
        else cpa_wait<0>();
        __syncthreads();
        const uint32_t stb = sb + (c & 1) * STG_B;
        const float* zs = (const float*)(dsm + (c & 1) * STG_B + 4 * RG_B);

        // ---- S = Q K^T (3-term split) ----
        float accS[8][4] = {};
#pragma unroll
        for (int kh = 0; kh < 4; kh++) {
#pragma unroll
            for (int jg = 0; jg < 4; jg++) {
                uint32_t off = (uint32_t)((jg * 16 + lrow) * FST + kh * 32 + lch * 16);
                uint32_t KH[4], KL[4];
                ldsm4(KH, stb + off);
                ldsm4(KL, stb + RG_B + off);
                mma_bf16(accS[jg * 2 + 0], qh[kh], KH[0], KH[2]);
                mma_bf16(accS[jg * 2 + 1], qh[kh], KH[1], KH[3]);
                mma_bf16(accS[jg * 2 + 0], qh[kh], KL[0], KL[2]);
                mma_bf16(accS[jg * 2 + 1], qh[kh], KL[1], KL[3]);
                mma_bf16(accS[jg * 2 + 0], ql[kh], KH[0], KH[2]);
                mma_bf16(accS[jg * 2 + 1], ql[kh], KH[1], KH[3]);
            }
        }

        // ---- scale + z (from smem), chunk max ----
        const int zr0 = wid * 16 + r, zr1 = zr0 + 8;
        float mc0 = -1e30f, mc1 = -1e30f;
#pragma unroll
        for (int nf = 0; nf < 8; nf++) {
            int col = nf * 8 + cq;
            float2 za = *(const float2*)&zs[zr0 * 68 + col];
            float2 zc = *(const float2*)&zs[zr1 * 68 + col];
            accS[nf][0] = fmaf(accS[nf][0], 0.125f, za.x);
            accS[nf][1] = fmaf(accS[nf][1], 0.125f, za.y);
            accS[nf][2] = fmaf(accS[nf][2], 0.125f, zc.x);
            accS[nf][3] = fmaf(accS[nf][3], 0.125f, zc.y);
            mc0 = fmaxf(mc0, fmaxf(accS[nf][0], accS[nf][1]));
            mc1 = fmaxf(mc1, fmaxf(accS[nf][2], accS[nf][3]));
        }
        mc0 = fmaxf(mc0, __shfl_xor_sync(0xffffffffu, mc0, 1));
        mc0 = fmaxf(mc0, __shfl_xor_sync(0xffffffffu, mc0, 2));
        mc1 = fmaxf(mc1, __shfl_xor_sync(0xffffffffu, mc1, 1));
        mc1 = fmaxf(mc1, __shfl_xor_sync(0xffffffffu, mc1, 2));
        float nm0 = fmaxf(m0, mc0), nm1 = fmaxf(m1, mc1);
        float sc0 = __expf(m0 - nm0), sc1 = __expf(m1 - nm1);
        m0 = nm0; m1 = nm1;
        l0 *= sc0; l1 *= sc1;
#pragma unroll
        for (int nf = 0; nf < 8; nf++) {
            accO[nf][0] *= sc0; accO[nf][1] *= sc0;
            accO[nf][2] *= sc1; accO[nf][3] *= sc1;
        }

        // ---- P = exp(S - m), pack A-frags hi/lo in registers ----
        uint32_t Ph[4][4], Pl[4][4];
#pragma unroll
        for (int kg = 0; kg < 4; kg++) {
#pragma unroll
            for (int half = 0; half < 2; half++) {
                int nf = kg * 2 + half;
                float p0 = __expf(accS[nf][0] - m0);
                float p1 = __expf(accS[nf][1] - m0);
                float p2 = __expf(accS[nf][2] - m1);
                float p3 = __expf(accS[nf][3] - m1);
                l0 += p0 + p1; l1 += p2 + p3;
                __nv_bfloat16 b0 = __float2bfloat16_rn(p0);
                __nv_bfloat16 b1 = __float2bfloat16_rn(p1);
                __nv_bfloat16 b2 = __float2bfloat16_rn(p2);
                __nv_bfloat16 b3 = __float2bfloat16_rn(p3);
                Ph[kg][half * 2 + 0] = pack2(b0, b1);
                Ph[kg][half * 2 + 1] = pack2(b2, b3);
                Pl[kg][half * 2 + 0] =
                    pack2(__float2bfloat16_rn(p0 - __bfloat162float(b0)),
                          __float2bfloat16_rn(p1 - __bfloat162float(b1)));
                Pl[kg][half * 2 + 1] =
                    pack2(__float2bfloat16_rn(p2 - __bfloat162float(b2)),
                          __float2bfloat16_rn(p3 - __bfloat162float(b3)));
            }
        }

        // ---- O += P V (3-term split) ----
#pragma unroll
        for (int kg = 0; kg < 4; kg++) {
#pragma unroll
            for (int ng = 0; ng < 4; ng++) {
                uint32_t voff = (uint32_t)((kg * 16 + lrow) * FST + ng * 32 + lch * 16);
                uint32_t VH[4], VL[4];
                ldsm4t(VH, stb + 2 * RG_B + voff);
                ldsm4t(VL, stb + 3 * RG_B + voff);
                mma_bf16(accO[ng * 2 + 0], Ph[kg], VH[0], VH[1]);
                mma_bf16(accO[ng * 2 + 1], Ph[kg], VH[2], VH[3]);
                mma_bf16(accO[ng * 2 + 0], Ph[kg], VL[0], VL[1]);
                mma_bf16(accO[ng * 2 + 1], Ph[kg], VL[2], VL[3]);
                mma_bf16(accO[ng * 2 + 0], Pl[kg], VH[0], VH[1]);
                mma_bf16(accO[ng * 2 + 1], Pl[kg], VH[2], VH[3]);
            }
        }
        __syncthreads();
    }
#undef KVISSUE

    l0 += __shfl_xor_sync(0xffffffffu, l0, 1);
    l0 += __shfl_xor_sync(0xffffffffu, l0, 2);
    l1 += __shfl_xor_sync(0xffffffffu, l1, 1);
    l1 += __shfl_xor_sync(0xffffffffu, l1, 2);
    float il0 = 1.0f / l0, il1 = 1.0f / l1;

    const int row0 = i0 + wid * 16 + r, row1 = row0 + 8;
#pragma unroll
    for (int nf = 0; nf < 8; nf++) {
        int col = h * ND + nf * 8 + cq;
        float2 ga = *(const float2*)(g_gt + (size_t)row0 * CS + col);
        float2 gb = *(const float2*)(g_gt + (size_t)row1 * CS + col);
        uint32_t hp, lp;
        split2(accO[nf][0] * il0 * ga.x, accO[nf][1] * il0 * ga.y, &hp, &lp);
        *(uint32_t*)(g_goh + (size_t)row0 * CS + col) = hp;
        *(uint32_t*)(g_gol + (size_t)row0 * CS + col) = lp;
        split2(accO[nf][2] * il1 * gb.x, accO[nf][3] * il1 * gb.y, &hp, &lp);
        *(uint32_t*)(g_goh + (size_t)row1 * CS + col) = hp;
        *(uint32_t*)(g_gol + (size_t)row1 * CS + col) = lp;
    }
}

// ---------------------------------------------------------------------------
extern "C" void kernel_launch(void* const* d_in, const int* in_sizes, int n_in,
                              void* d_out, int out_size)
{
    (void)in_sizes; (void)n_in; (void)out_size;
    const float* s    = (const float*)d_in[0];
    const float* k_in = (const float*)d_in[1];
    const float* mask = (const float*)d_in[2];
    const float* bias = (const float*)d_in[3];
    const float* bq   = (const float*)d_in[5];
    const float* Wz   = (const float*)d_in[10];
    float* out = (float*)d_out;

    float* z;
    cudaGetSymbolAddress((void**)&z, g_z);

    cudaFuncSetAttribute(fused_pz,   cudaFuncAttributeMaxDynamicSharedMemorySize,
                         GEMM_SMEM);
    cudaFuncSetAttribute(mma_gated,  cudaFuncAttributeMaxDynamicSharedMemorySize,
                         GATED_SMEM);
    cudaFuncSetAttribute(attn_flash, cudaFuncAttributeMaxDynamicSharedMemorySize,
                         AT_SMEM);

    // split inputs + weights to bf16 hi/lo once
    preconv<<<dim3(128, 7), 256>>>(s, k_in, (const float*)d_in[4],
                                   (const float*)d_in[6], (const float*)d_in[7],
                                   (const float*)d_in[8], (const float*)d_in[9]);
    // projections + z projection (concatenated mapping; 3-stage pipeline)
    fused_pz<<<512 + 4096, 256, GEMM_SMEM>>>(bq, bias, Wz, mask, z);
    // flash attention (online softmax, z staged via cp.async)
    attn_flash<<<dim3(NI / 64, NH), 128, AT_SMEM>>>(z);
    // gated output projection (256 blocks, 128x32 tiles, 3-stage)
    mma_gated<<<dim3(32, 8), 256, GATED_SMEM>>>(out);
}

// round 15
// speedup vs baseline: 1.1715x; 1.0531x over previous
#include <cuda_runtime.h>
#include <cuda_bf16.h>
#include <stdint.h>
#include <math.h>

#define CS 1024
#define NI 1024
#define NJ 1024
#define NH 16
#define ND 64
#define CZ 128

// ---------------- scratch (device globals; no allocation allowed) ----------
__device__ float g_gt[NI * CS];                       // sigmoid gate (fp32)
__device__ float g_z[(size_t)NH * NI * NJ];           // pair bias [h][i*NJ+j]
__device__ __nv_bfloat16 g_sh[NI * CS],  g_sl[NI * CS];
__device__ __nv_bfloat16 g_kih[NJ * CS], g_kil[NJ * CS];
__device__ __nv_bfloat16 g_Wqh[CS * CS], g_Wql[CS * CS];
__device__ __nv_bfloat16 g_Wkh[CS * CS], g_Wkl[CS * CS];
__device__ __nv_bfloat16 g_Wvh[CS * CS], g_Wvl[CS * CS];
__device__ __nv_bfloat16 g_Wgh[CS * CS], g_Wgl[CS * CS];
__device__ __nv_bfloat16 g_Woh[CS * CS], g_Wol[CS * CS];
__device__ __nv_bfloat16 g_qh[NI * CS],  g_ql[NI * CS];
__device__ __nv_bfloat16 g_kh[NJ * CS],  g_kl[NJ * CS];
__device__ __nv_bfloat16 g_vh[NJ * CS],  g_vl[NJ * CS];
__device__ __nv_bfloat16 g_goh[NI * CS], g_gol[NI * CS];

// ===================== mma.sync / cp.async helpers =========================
__device__ __forceinline__ uint32_t smem_u32(const void* p) {
    uint32_t r;
    asm("{ .reg .u64 t; cvta.to.shared.u64 t, %1; cvt.u32.u64 %0, t; }"
        : "=r"(r) : "l"(p));
    return r;
}
__device__ __forceinline__ void ldsm4(uint32_t* r, uint32_t a) {
    asm volatile("ldmatrix.sync.aligned.m8n8.x4.shared.b16 {%0,%1,%2,%3}, [%4];"
                 : "=r"(r[0]), "=r"(r[1]), "=r"(r[2]), "=r"(r[3]) : "r"(a));
}
__device__ __forceinline__ void ldsm4t(uint32_t* r, uint32_t a) {
    asm volatile("ldmatrix.sync.aligned.m8n8.x4.trans.shared.b16 {%0,%1,%2,%3}, [%4];"
                 : "=r"(r[0]), "=r"(r[1]), "=r"(r[2]), "=r"(r[3]) : "r"(a));
}
__device__ __forceinline__ void mma_bf16(float* d, const uint32_t* a,
                                         uint32_t b0, uint32_t b1) {
    asm volatile(
        "mma.sync.aligned.m16n8k16.row.col.f32.bf16.bf16.f32 "
        "{%0,%1,%2,%3}, {%4,%5,%6,%7}, {%8,%9}, {%0,%1,%2,%3};"
        : "+f"(d[0]), "+f"(d[1]), "+f"(d[2]), "+f"(d[3])
        : "r"(a[0]), "r"(a[1]), "r"(a[2]), "r"(a[3]), "r"(b0), "r"(b1));
}
__device__ __forceinline__ void cpa16(uint32_t s, const void* g) {
    asm volatile("cp.async.cg.shared.global [%0], [%1], 16;" :: "r"(s), "l"(g));
}
__device__ __forceinline__ void cpa_commit() {
    asm volatile("cp.async.commit_group;");
}
template <int N> __device__ __forceinline__ void cpa_wait() {
    asm volatile("cp.async.wait_group %0;" :: "n"(N));
}
__device__ __forceinline__ uint32_t pack2(__nv_bfloat16 a, __nv_bfloat16 b) {
    return (uint32_t)__bfloat16_as_ushort(a) |
           ((uint32_t)__bfloat16_as_ushort(b) << 16);
}
__device__ __forceinline__ void split4(float4 v, uint2* hi, uint2* lo) {
    __nv_bfloat16 h0 = __float2bfloat16_rn(v.x);
    __nv_bfloat16 h1 = __float2bfloat16_rn(v.y);
    __nv_bfloat16 h2 = __float2bfloat16_rn(v.z);
    __nv_bfloat16 h3 = __float2bfloat16_rn(v.w);
    hi->x = pack2(h0, h1); hi->y = pack2(h2, h3);
    lo->x = pack2(__float2bfloat16_rn(v.x - __bfloat162float(h0)),
                  __float2bfloat16_rn(v.y - __bfloat162float(h1)));
    lo->y = pack2(__float2bfloat16_rn(v.z - __bfloat162float(h2)),
                  __float2bfloat16_rn(v.w - __bfloat162float(h3)));
}
__device__ __forceinline__ void split2(float v0, float v1,
                                       uint32_t* hp, uint32_t* lp) {
    __nv_bfloat16 h0 = __float2bfloat16_rn(v0);
    __nv_bfloat16 h1 = __float2bfloat16_rn(v1);
    *hp = pack2(h0, h1);
    *lp = pack2(__float2bfloat16_rn(v0 - __bfloat162float(h0)),
                __float2bfloat16_rn(v1 - __bfloat162float(h1)));
}

// ============ preconvert: fp32 -> bf16 hi/lo for 7 matrices (1M each) ======
__global__ __launch_bounds__(256) void preconv(
    const float* __restrict__ s, const float* __restrict__ kin,
    const float* __restrict__ Wq, const float* __restrict__ Wk,
    const float* __restrict__ Wv, const float* __restrict__ Wg,
    const float* __restrict__ Wo)
{
    const float* src; __nv_bfloat16 *dh, *dl;
    switch (blockIdx.y) {
        case 0: src = s;   dh = g_sh;  dl = g_sl;  break;
        case 1: src = kin; dh = g_kih; dl = g_kil; break;
        case 2: src = Wq;  dh = g_Wqh; dl = g_Wql; break;
        case 3: src = Wk;  dh = g_Wkh; dl = g_Wkl; break;
        case 4: src = Wv;  dh = g_Wvh; dl = g_Wvl; break;
        case 5: src = Wg;  dh = g_Wgh; dl = g_Wgl; break;
        default: src = Wo; dh = g_Woh; dl = g_Wol; break;
    }
    const int stride = gridDim.x * 256;
    for (int i = blockIdx.x * 256 + threadIdx.x; i < (CS * CS) / 4; i += stride) {
        float4 v = ((const float4*)src)[i];
        uint2 hi, lo; split4(v, &hi, &lo);
        ((uint2*)dh)[i] = hi;
        ((uint2*)dl)[i] = lo;
    }
}

// ====== bf16-split GEMM (templated BN, NST stages) =========================
#define ASTR 80
#define SA_BYTES (128 * ASTR)

#define EP_F32 0
#define EP_PAIR 1
#define EP_PAIR_BIAS 2
#define EP_F32_SIG 3

template <int BN, int NST>
__device__ __forceinline__ void gemm_bf16_body(
    const __nv_bfloat16* __restrict__ Ah, const __nv_bfloat16* __restrict__ Al,
    const __nv_bfloat16* __restrict__ Bh, const __nv_bfloat16* __restrict__ Bl,
    const float* __restrict__ bias, int mode,
    float* __restrict__ Cf, __nv_bfloat16* __restrict__ Ch,
    __nv_bfloat16* __restrict__ Cl, int bm, int bn, uint8_t* dsm)
{
    constexpr int SBB = BN * ASTR;
    constexpr int STG = 2 * SA_BYTES + 2 * SBB;
    constexpr int NF = BN / 16;
    constexpr int GI = BN / 32;
    const uint32_t sb = smem_u32(dsm);

    const int tid = threadIdx.x, wid = tid >> 5, lane = tid & 31;
    const int wm = (wid & 3) * 32, wn = (wid >> 2) * (BN / 2);
    const int lrow = lane & 15, lch = lane >> 4;

    float acc[2][NF][4];
#pragma unroll
    for (int a = 0; a < 2; a++)
#pragma unroll
        for (int b = 0; b < NF; b++)
#pragma unroll
            for (int e = 0; e < 4; e++) acc[a][b][e] = 0.f;

    auto issue = [&](int c, int st) {
        uint32_t stb = sb + st * STG;
#pragma unroll
        for (int i = 0; i < 4; i++) {
            int u = tid + i * 256; int arr = u >> 9; int rem = u & 511;
            int row = rem >> 2, un = rem & 3;
            const __nv_bfloat16* gp = (arr ? Al : Ah) +
                (size_t)(bm + row) * CS + c * 32 + un * 8;
            cpa16(stb + arr * SA_BYTES + row * ASTR + un * 16, gp);
        }
#pragma unroll
        for (int i = 0; i < BN / 32; i++) {
            int u = tid + i * 256; int arr = u / (BN * 4); int rem = u % (BN * 4);
            int row = rem >> 2, un = rem & 3;
            const __nv_bfloat16* gp = (arr ? Bl : Bh) +
                (size_t)(bn + row) * CS + c * 32 + un * 8;
            cpa16(stb + 2 * SA_BYTES + arr * SBB + row * ASTR + un * 16, gp);
        }
    };

#pragma unroll
    for (int s = 0; s < NST - 1; s++) { issue(s, s); cpa_commit(); }

    for (int c = 0; c < 32; c++) {
        cpa_wait<NST - 2>();
        __syncthreads();
        if (c + NST - 1 < 32) { issue(c + NST - 1, (c + NST - 1) % NST); cpa_commit(); }

        const uint32_t stb = sb + (c % NST) * STG;
#pragma unroll
        for (int kh = 0; kh < 2; kh++) {
            uint32_t Af[2][4], Af2[2][4], Bf[GI][4], Bf2[GI][4];
#pragma unroll
            for (int mf = 0; mf < 2; mf++) {
                uint32_t off = (uint32_t)((wm + mf * 16 + lrow) * ASTR + kh * 32 + lch * 16);
                ldsm4(Af[mf],  stb + off);
                ldsm4(Af2[mf], stb + SA_BYTES + off);
            }
#pragma unroll
            for (int gi = 0; gi < GI; gi++) {
                uint32_t off = (uint32_t)((wn + gi * 16 + lrow) * ASTR + kh * 32 + lch * 16);
                ldsm4(Bf[gi],  stb + 2 * SA_BYTES + off);
                ldsm4(Bf2[gi], stb + 2 * SA_BYTES + SBB + off);
            }
#pragma unroll
            for (int mf = 0; mf < 2; mf++)
#pragma unroll
                for (int nf = 0; nf < NF; nf++) {
                    int gi = nf >> 1, s2 = nf & 1;
                    mma_bf16(acc[mf][nf], Af[mf],  Bf[gi][s2],  Bf[gi][s2 + 2]);
                    mma_bf16(acc[mf][nf], Af[mf],  Bf2[gi][s2], Bf2[gi][s2 + 2]);
                    mma_bf16(acc[mf][nf], Af2[mf], Bf[gi][s2],  Bf[gi][s2 + 2]);
                }
        }
    }

#pragma unroll
    for (int mf = 0; mf < 2; mf++)
#pragma unroll
        for (int nf = 0; nf < NF; nf++) {
            int col = bn + wn + nf * 8 + (lane & 3) * 2;
#pragma unroll
            for (int rh = 0; rh < 2; rh++) {
                int row = bm + wm + mf * 16 + (lane >> 2) + rh * 8;
                float v0 = acc[mf][nf][rh * 2 + 0];
                float v1 = acc[mf][nf][rh * 2 + 1];
                if (mode == EP_PAIR_BIAS) { v0 += bias[col]; v1 += bias[col + 1]; }
                if (mode == EP_F32_SIG) {
                    v0 = 1.0f / (1.0f + __expf(-v0));
                    v1 = 1.0f / (1.0f + __expf(-v1));
                }
                if (mode == EP_F32 || mode == EP_F32_SIG) {
                    float2 st2; st2.x = v0; st2.y = v1;
                    *(float2*)(Cf + (size_t)row * CS + col) = st2;
                } else {
                    uint32_t hp, lp; split2(v0, v1, &hp, &lp);
                    *(uint32_t*)(Ch + (size_t)row * CS + col) = hp;
                    *(uint32_t*)(Cl + (size_t)row * CS + col) = lp;
                }
            }
        }
}

#define PROJ_SMEM (2 * (2 * SA_BYTES + 2 * 128 * ASTR))  // 81920 (BN=128, 2-stage)
#define GATED_SMEM (3 * (2 * SA_BYTES + 2 * 32 * ASTR))  // 76800 (BN=32, 3-stage)

// ============ z body (256 threads = two independent 128-thread groups) =====
#define ZG_BYTES (2 * 128 * ASTR + 2 * 16 * 272)   // 29184 per group

__device__ __forceinline__ void z_body256(
    uint8_t* dsm, const float* __restrict__ bias, const float* __restrict__ Wz,
    const float* __restrict__ mask, float* __restrict__ z, size_t bm0)
{
    const int tid = threadIdx.x;
    const int grp = tid >> 7;
    const int gtid = tid & 127;
    const int wid = gtid >> 5, lane = gtid & 31;
    const size_t bm = bm0 + (size_t)grp * 128;
    const int wm = wid * 32;
    const int lrow = lane & 15, lch = lane >> 4;

    uint8_t* base = dsm + grp * ZG_BYTES;
    uint8_t* sAh = base;
    uint8_t* sAl = base + 128 * ASTR;
    uint8_t* sWh = base + 2 * 128 * ASTR;
    uint8_t* sWl = base + 2 * 128 * ASTR + 16 * 272;

#pragma unroll
    for (int i = 0; i < 16; i++) {
        int idx = gtid + i * 128;
        int h = idx >> 7, c = idx & 127;
        float v = Wz[c * NH + h];
        __nv_bfloat16 hb = __float2bfloat16_rn(v);
        *(uint16_t*)(sWh + h * 272 + c * 2) = __bfloat16_as_ushort(hb);
        *(uint16_t*)(sWl + h * 272 + c * 2) =
            __bfloat16_as_ushort(__float2bfloat16_rn(v - __bfloat162float(hb)));
    }

    float acc[2][2][4] = {};
    float4 ra[8];

#define ZLOAD(c) do {                                                          \
    _Pragma("unroll")                                                          \
    for (int i = 0; i < 8; i++) {                                              \
        int slot = gtid + i * 128; int row = slot >> 3, qq = slot & 7;         \
        ra[i] = *(const float4*)(bias + (bm + row) * CZ + (c) * 32 + qq * 4);  \
    } } while (0)

    ZLOAD(0);
    for (int c = 0; c < 4; c++) {
        __syncthreads();
#pragma unroll
        for (int i = 0; i < 8; i++) {
            int slot = gtid + i * 128; int row = slot >> 3, qq = slot & 7;
            uint2 hi, lo; split4(ra[i], &hi, &lo);
            *(uint2*)(sAh + row * ASTR + qq * 8) = hi;
            *(uint2*)(sAl + row * ASTR + qq * 8) = lo;
        }
        __syncthreads();
        if (c < 3) ZLOAD(c + 1);

#pragma unroll
        for (int kh = 0; kh < 2; kh++) {
            uint32_t Wh[4], Wl[4];
            uint32_t woff = (uint32_t)(lrow * 272 + c * 64 + kh * 32 + lch * 16);
            ldsm4(Wh, smem_u32(sWh) + woff);
            ldsm4(Wl, smem_u32(sWl) + woff);
#pragma unroll
            for (int mf = 0; mf < 2; mf++) {
                uint32_t Ah[4], Al[4];
                uint32_t off = (uint32_t)((wm + mf * 16 + lrow) * ASTR + kh * 32 + lch * 16);
                ldsm4(Ah, smem_u32(sAh) + off);
                ldsm4(Al, smem_u32(sAl) + off);
#pragma unroll
                for (int nf = 0; nf < 2; nf++) {
                    mma_bf16(acc[mf][nf], Ah, Wh[nf], Wh[nf + 2]);
                    mma_bf16(acc[mf][nf], Ah, Wl[nf], Wl[nf + 2]);
                    mma_bf16(acc[mf][nf], Al, Wh[nf], Wh[nf + 2]);
                }
            }
        }
    }
#undef ZLOAD

#pragma unroll
    for (int mf = 0; mf < 2; mf++)
#pragma unroll
        for (int rh = 0; rh < 2; rh++) {
            size_t m = bm + wm + mf * 16 + (lane >> 2) + rh * 8;
            float mterm = (1.0f - mask[m & (NJ - 1)]) * (-1000000.0f);
#pragma unroll
            for (int nf = 0; nf < 2; nf++) {
                int h0 = nf * 8 + (lane & 3) * 2;
                z[(size_t)h0 * ((size_t)NI * NJ) + m]       = acc[mf][nf][rh * 2 + 0] + mterm;
                z[(size_t)(h0 + 1) * ((size_t)NI * NJ) + m] = acc[mf][nf][rh * 2 + 1] + mterm;
            }
        }
}

// ============ fused proj + z (concatenated; proj = 128x128 single wave) ====
__global__ __launch_bounds__(256, 2) void fused_pz(
    const float* __restrict__ bq, const float* __restrict__ bias,
    const float* __restrict__ Wz, const float* __restrict__ mask,
    float* __restrict__ z)
{
    extern __shared__ __align__(16) uint8_t dsm[];
    const int t = blockIdx.x;
    if (t < 256) {
        const int pid = t >> 6, rem = t & 63;
        const int bn = (rem & 7) * 128, bm = (rem >> 3) * 128;
        switch (pid) {
            case 0:
                gemm_bf16_body<128, 2>(g_sh, g_sl, g_Wqh, g_Wql, bq, EP_PAIR_BIAS,
                                       nullptr, g_qh, g_ql, bm, bn, dsm);
                break;
            case 1:
                gemm_bf16_body<128, 2>(g_kih, g_kil, g_Wkh, g_Wkl, nullptr, EP_PAIR,
                                       nullptr, g_kh, g_kl, bm, bn, dsm);
                break;
            case 2:
                gemm_bf16_body<128, 2>(g_kih, g_kil, g_Wvh, g_Wvl, nullptr, EP_PAIR,
                                       nullptr, g_vh, g_vl, bm, bn, dsm);
                break;
            default:
                gemm_bf16_body<128, 2>(g_sh, g_sl, g_Wgh, g_Wgl, nullptr, EP_F32_SIG,
                                       g_gt, nullptr, nullptr, bm, bn, dsm);
                break;
        }
    } else {
        z_body256(dsm, bias, Wz, mask, z, (size_t)(t - 256) * 256);
    }
}

// ============ gated output projection: 128x32 tiles, 256 blocks ============
__global__ __launch_bounds__(256, 2) void mma_gated(float* __restrict__ out)
{
    extern __shared__ __align__(16) uint8_t dsm[];
    gemm_bf16_body<32, 3>(g_goh, g_gol, g_Woh, g_Wol, nullptr, EP_F32,
                          out, nullptr, nullptr, blockIdx.y * 128, blockIdx.x * 32,
                          dsm);
}

// ============ flash attention: block = 64 i x 1 head, 4 warps ==============
#define FST 144
#define RG_B (64 * FST)
#define ZST 272
#define ZRG (64 * ZST)
#define STG_B (4 * RG_B + ZRG)
#define AT_SMEM (2 * STG_B)

__global__ __launch_bounds__(128, 2) void attn_flash(const float* __restrict__ z)
{
    extern __shared__ __align__(16) uint8_t dsm[];
    const uint32_t sb = smem_u32(dsm);
    const int tid = threadIdx.x, wid = tid >> 5, lane = tid & 31;
    const int i0 = blockIdx.x * 64;
    const int h  = blockIdx.y;
    const int lrow = lane & 15, lch = lane >> 4;
    const int r   = lane >> 2;
    const int cq  = (lane & 3) * 2;
    const float* zh = z + (size_t)h * ((size_t)NI * NJ);

    for (int i = tid; i < 1024; i += 128) {
        int un = i & 7, row = (i >> 3) & 63, rg = i >> 9;
        const __nv_bfloat16* src = (rg ? g_ql : g_qh) +
            (size_t)(i0 + row) * CS + h * ND + un * 8;
        cpa16(sb + rg * RG_B + row * FST + un * 16, src);
    }
    cpa_commit(); cpa_wait<0>(); __syncthreads();
    uint32_t qh[4][4], ql[4][4];
#pragma unroll
    for (int kh = 0; kh < 4; kh++) {
        uint32_t off = (uint32_t)((wid * 16 + lrow) * FST + kh * 32 + lch * 16);
        ldsm4(qh[kh], sb + off);
        ldsm4(ql[kh], sb + RG_B + off);
    }
    __syncthreads();

    float accO[8][4] = {};
    float m0 = -1e30f, m1 = -1e30f, l0 = 0.f, l1 = 0.f;

#define KVISSUE(c) do {                                                        \
    uint32_t stb_ = sb + ((c) & 1) * STG_B;                                    \
    for (int i = tid; i < 2048; i += 128) {                                    \
        int un = i & 7, row = (i >> 3) & 63, rg = i >> 9;                      \
        const __nv_bfloat16* src;                                              \
        switch (rg) { case 0: src = g_kh; break; case 1: src = g_kl; break;    \
                      case 2: src = g_vh; break; default: src = g_vl; }        \
        src += (size_t)((c) * 64 + row) * CS + h * ND + un * 8;                \
        cpa16(stb_ + rg * RG_B + row * FST + un * 16, src);                    \
    }                                                                          \
    for (int i = tid; i < 1024; i += 128) {                                    \
        int row = i >> 4, un = i & 15;                                         \
        const float* zsrc = zh + (size_t)(i0 + row) * NJ + (c) * 64 + un * 4;  \
        cpa16(stb_ + 4 * RG_B + row * ZST + un * 16, zsrc);                    \
    } } while (0)

    KVISSUE(0); cpa_commit();

    for (int c = 0; c < 16; c++) {
        if (c < 15) { KVISSUE(c + 1); cpa_commit(); cpa_wait<1>(); }
        else cpa_wait<0>();
        __syncthreads();
        const uint32_t stb = sb + (c & 1) * STG_B;
        const float* zs = (const float*)(dsm + (c & 1) * STG_B + 4 * RG_B);

        float accS[8][4] = {};
#pragma unroll
        for (int kh = 0; kh < 4; kh++) {
#pragma unroll
            for (int jg = 0; jg < 4; jg++) {
                uint32_t off = (uint32_t)((jg * 16 + lrow) * FST + kh * 32 + lch * 16);
                uint32_t KH[4], KL[4];
                ldsm4(KH, stb + off);
                ldsm4(KL, stb + RG_B + off);
                mma_bf16(accS[jg * 2 + 0], qh[kh], KH[0], KH[2]);
                mma_bf16(accS[jg * 2 + 1], qh[kh], KH[1], KH[3]);
                mma_bf16(accS[jg * 2 + 0], qh[kh], KL[0], KL[2]);
                mma_bf16(accS[jg * 2 + 1], qh[kh], KL[1], KL[3]);
                mma_bf16(accS[jg * 2 + 0], ql[kh], KH[0], KH[2]);
                mma_bf16(accS[jg * 2 + 1], ql[kh], KH[1], KH[3]);
            }
        }

        const int zr0 = wid * 16 + r, zr1 = zr0 + 8;
        float mc0 = -1e30f, mc1 = -1e30f;
#pragma unroll
        for (int nf = 0; nf < 8; nf++) {
            int col = nf * 8 + cq;
            float2 za = *(const float2*)&zs[zr0 * 68 + col];
            float2 zc = *(const float2*)&zs[zr1 * 68 + col];
            accS[nf][0] = fmaf(accS[nf][0], 0.125f, za.x);
            accS[nf][1] = fmaf(accS[nf][1], 0.125f, za.y);
            accS[nf][2] = fmaf(accS[nf][2], 0.125f, zc.x);
            accS[nf][3] = fmaf(accS[nf][3], 0.125f, zc.y);
            mc0 = fmaxf(mc0, fmaxf(accS[nf][0], accS[nf][1]));
            mc1 = fmaxf(mc1, fmaxf(accS[nf][2], accS[nf][3]));
        }
        mc0 = fmaxf(mc0, __shfl_xor_sync(0xffffffffu, mc0, 1));
        mc0 = fmaxf(mc0, __shfl_xor_sync(0xffffffffu, mc0, 2));
        mc1 = fmaxf(mc1, __shfl_xor_sync(0xffffffffu, mc1, 1));
        mc1 = fmaxf(mc1, __shfl_xor_sync(0xffffffffu, mc1, 2));
        float nm0 = fmaxf(m0, mc0), nm1 = fmaxf(m1, mc1);
        float sc0 = __expf(m0 - nm0), sc1 = __expf(m1 - nm1);
        m0 = nm0; m1 = nm1;
        l0 *= sc0; l1 *= sc1;
#pragma unroll
        for (int nf = 0; nf < 8; nf++) {
            accO[nf][0] *= sc0; accO[nf][1] *= sc0;
            accO[nf][2] *= sc1; accO[nf][3] *= sc1;
        }

        uint32_t Ph[4][4], Pl[4][4];
#pragma unroll
        for (int kg = 0; kg < 4; kg++) {
#pragma unroll
            for (int half = 0; half < 2; half++) {
                int nf = kg * 2 + half;
                float p0 = __expf(accS[nf][0] - m0);
                float p1 = __expf(accS[nf][1] - m0);
                float p2 = __expf(accS[nf][2] - m1);
                float p3 = __expf(accS[nf][3] - m1);
                l0 += p0 + p1; l1 += p2 + p3;
                __nv_bfloat16 b0 = __float2bfloat16_rn(p0);
                __nv_bfloat16 b1 = __float2bfloat16_rn(p1);
                __nv_bfloat16 b2 = __float2bfloat16_rn(p2);
                __nv_bfloat16 b3 = __float2bfloat16_rn(p3);
                Ph[kg][half * 2 + 0] = pack2(b0, b1);
                Ph[kg][half * 2 + 1] = pack2(b2, b3);
                Pl[kg][half * 2 + 0] =
                    pack2(__float2bfloat16_rn(p0 - __bfloat162float(b0)),
                          __float2bfloat16_rn(p1 - __bfloat162float(b1)));
                Pl[kg][half * 2 + 1] =
                    pack2(__float2bfloat16_rn(p2 - __bfloat162float(b2)),
                          __float2bfloat16_rn(p3 - __bfloat162float(b3)));
            }
        }

#pragma unroll
        for (int kg = 0; kg < 4; kg++) {
#pragma unroll
            for (int ng = 0; ng < 4; ng++) {
                uint32_t voff = (uint32_t)((kg * 16 + lrow) * FST + ng * 32 + lch * 16);
                uint32_t VH[4], VL[4];
                ldsm4t(VH, stb + 2 * RG_B + voff);
                ldsm4t(VL, stb + 3 * RG_B + voff);
                mma_bf16(accO[ng * 2 + 0], Ph[kg], VH[0], VH[1]);
                mma_bf16(accO[ng * 2 + 1], Ph[kg], VH[2], VH[3]);
                mma_bf16(accO[ng * 2 + 0], Ph[kg], VL[0], VL[1]);
                mma_bf16(accO[ng * 2 + 1], Ph[kg], VL[2], VL[3]);
                mma_bf16(accO[ng * 2 + 0], Pl[kg], VH[0], VH[1]);
                mma_bf16(accO[ng * 2 + 1], Pl[kg], VH[2], VH[3]);
            }
        }
        __syncthreads();
    }
#undef KVISSUE

    l0 += __shfl_xor_sync(0xffffffffu, l0, 1);
    l0 += __shfl_xor_sync(0xffffffffu, l0, 2);
    l1 += __shfl_xor_sync(0xffffffffu, l1, 1);
    l1 += __shfl_xor_sync(0xffffffffu, l1, 2);
    float il0 = 1.0f / l0, il1 = 1.0f / l1;

    const int row0 = i0 + wid * 16 + r, row1 = row0 + 8;
#pragma unroll
    for (int nf = 0; nf < 8; nf++) {
        int col = h * ND + nf * 8 + cq;
        float2 ga = *(const float2*)(g_gt + (size_t)row0 * CS + col);
        float2 gb = *(const float2*)(g_gt + (size_t)row1 * CS + col);
        uint32_t hp, lp;
        split2(accO[nf][0] * il0 * ga.x, accO[nf][1] * il0 * ga.y, &hp, &lp);
        *(uint32_t*)(g_goh + (size_t)row0 * CS + col) = hp;
        *(uint32_t*)(g_gol + (size_t)row0 * CS + col) = lp;
        split2(accO[nf][2] * il1 * gb.x, accO[nf][3] * il1 * gb.y, &hp, &lp);
        *(uint32_t*)(g_goh + (size_t)row1 * CS + col) = hp;
        *(uint32_t*)(g_gol + (size_t)row1 * CS + col) = lp;
    }
}

// ---------------------------------------------------------------------------
extern "C" void kernel_launch(void* const* d_in, const int* in_sizes, int n_in,
                              void* d_out, int out_size)
{
    (void)in_sizes; (void)n_in; (void)out_size;
    const float* s    = (const float*)d_in[0];
    const float* k_in = (const float*)d_in[1];
    const float* mask = (const float*)d_in[2];
    const float* bias = (const float*)d_in[3];
    const float* bq   = (const float*)d_in[5];
    const float* Wz   = (const float*)d_in[10];
    float* out = (float*)d_out;

    float* z;
    cudaGetSymbolAddress((void**)&z, g_z);

    cudaFuncSetAttribute(fused_pz,   cudaFuncAttributeMaxDynamicSharedMemorySize,
                         PROJ_SMEM);
    cudaFuncSetAttribute(mma_gated,  cudaFuncAttributeMaxDynamicSharedMemorySize,
                         GATED_SMEM);
    cudaFuncSetAttribute(attn_flash, cudaFuncAttributeMaxDynamicSharedMemorySize,
                         AT_SMEM);

    // split inputs + weights to bf16 hi/lo once
    preconv<<<dim3(128, 7), 256>>>(s, k_in, (const float*)d_in[4],
                                   (const float*)d_in[6], (const float*)d_in[7],
                                   (const float*)d_in[8], (const float*)d_in[9]);
    // projections (128x128 tiles, single wave) + z projection
    fused_pz<<<256 + 4096, 256, PROJ_SMEM>>>(bq, bias, Wz, mask, z);
    // flash attention (online softmax, z staged via cp.async)
    attn_flash<<<dim3(NI / 64, NH), 128, AT_SMEM>>>(z);
    // gated output projection (256 blocks, 128x32 tiles, 3-stage)
    mma_gated<<<dim3(32, 8), 256, GATED_SMEM>>>(out);
}